// round 2
// baseline (speedup 1.0000x reference)
#include <cuda_runtime.h>
#include <cuda_bf16.h>

// Problem constants
#define BATCH   32
#define NATOMS  1024
#define ITILE   4          // output rows per block
#define THREADS 256

// Minimum-image wrap matching XLA numerics exactly:
// IEEE round-to-nearest divide, rint (ties to even), then fused a - n*L.
__device__ __forceinline__ float min_image(float d, float L)
{
    return __fmaf_rn(-rintf(__fdiv_rn(d, L)), L, d);
}

// Each block: one frame b, ITILE consecutive i-rows.
// Row = 1024 atoms * 3 floats = 3072 floats = 768 float4s.
// Thread t issues stores s=0..2 at float4 index q = s*256 + t, so every
// warp-level STG.128 covers a contiguous 512B span (4 lines — minimum).
// Each float4 straddles two atoms (16B vs 12B/atom): compute both atoms'
// 6 components and select 4 by r = (4q) mod 3.
__global__ __launch_bounds__(THREADS)
void rij_min_image_kernel(const float* __restrict__ pos,
                          const float* __restrict__ cell,
                          float* __restrict__ out)
{
    __shared__ float sx[NATOMS], sy[NATOMS], sz[NATOMS];   // SoA, 12 KB

    const int b  = blockIdx.y;
    const int i0 = blockIdx.x * ITILE;

    // Cooperative SoA fill of this frame's positions.
    const float* pb = pos + (size_t)b * NATOMS * 3;
    #pragma unroll
    for (int a = threadIdx.x; a < NATOMS; a += THREADS) {
        sx[a] = pb[3 * a + 0];
        sy[a] = pb[3 * a + 1];
        sz[a] = pb[3 * a + 2];
    }

    // Box lengths from the cell diagonal.
    const float Lx = cell[(size_t)b * 9 + 0];
    const float Ly = cell[(size_t)b * 9 + 4];
    const float Lz = cell[(size_t)b * 9 + 8];

    __syncthreads();

    // Row-atom positions, cached across the whole block of stores.
    float pix[ITILE], piy[ITILE], piz[ITILE];
    #pragma unroll
    for (int ii = 0; ii < ITILE; ++ii) {
        pix[ii] = sx[i0 + ii];
        piy[ii] = sy[i0 + ii];
        piz[ii] = sz[i0 + ii];
    }

    float* orow = out + ((size_t)b * NATOMS * NATOMS + (size_t)i0 * NATOMS) * 3;

    #pragma unroll
    for (int s = 0; s < 3; ++s) {
        const int q  = s * THREADS + threadIdx.x;   // float4 index in row, 0..767
        const int f0 = 4 * q;                       // first float index
        const int ja = f0 / 3;                      // first atom (<= 1022)
        const int r  = f0 - 3 * ja;                 // 0, 1, or 2

        // Two consecutive column atoms, cached across the ITILE rows.
        const float ax = sx[ja],     ay = sy[ja],     az = sz[ja];
        const float bx = sx[ja + 1], by = sy[ja + 1], bz = sz[ja + 1];

        #pragma unroll
        for (int ii = 0; ii < ITILE; ++ii) {
            const float d0 = min_image(pix[ii] - ax, Lx);
            const float d1 = min_image(piy[ii] - ay, Ly);
            const float d2 = min_image(piz[ii] - az, Lz);
            const float d3 = min_image(pix[ii] - bx, Lx);
            const float d4 = min_image(piy[ii] - by, Ly);
            const float d5 = min_image(piz[ii] - bz, Lz);

            float4 v;
            v.x = (r == 0) ? d0 : ((r == 1) ? d1 : d2);
            v.y = (r == 0) ? d1 : ((r == 1) ? d2 : d3);
            v.z = (r == 0) ? d2 : ((r == 1) ? d3 : d4);
            v.w = (r == 0) ? d3 : ((r == 1) ? d4 : d5);

            __stcs((float4*)(orow + (size_t)ii * NATOMS * 3) + q, v);
        }
    }
}

extern "C" void kernel_launch(void* const* d_in, const int* in_sizes, int n_in,
                              void* d_out, int out_size)
{
    const float* positions = (const float*)d_in[0];  // (32, 1024, 3)
    const float* cell      = (const float*)d_in[1];  // (32, 3, 3)
    float* out             = (float*)d_out;          // (32, 1024, 1024, 3)

    dim3 grid(NATOMS / ITILE, BATCH);   // (256, 32) = 8192 blocks
    rij_min_image_kernel<<<grid, THREADS>>>(positions, cell, out);
}

// round 3
// speedup vs baseline: 2.0090x; 2.0090x over previous
#include <cuda_runtime.h>
#include <cuda_bf16.h>

// Problem constants
#define BATCH   32
#define NATOMS  1024
#define ITILE   4          // output rows per block
#define THREADS 256

// Minimum-image wrap WITHOUT the divide, bit-exact vs the reference's
// rintf(__fdiv_rn(d, L)) * L for |d| < L:
//   rn(d/L) > 0.5  <=>  d > L/2   (no representable float in the gap;
//                                  tie at d == L/2 exactly gives rint = 0)
// so n = rint(d/L) is just a two-sided threshold on d. L/2 is exact in
// binary FP. n in {-1, 0, +1} since |d| < L. d - n*L is then one FADD
// (exact same value as the reference's fused form for n in {-1,0,1}:
//  fma(-n, L, d) with n=+-1 is d -+ L, with n=0 is d).
__device__ __forceinline__ float min_image(float d, float L, float hl)
{
    float r = d;
    if (d >  hl) r = d - L;
    if (d < -hl) r = d + L;
    return r;
}

// Each block: one frame b, ITILE consecutive i-rows.
// Row = 1024 atoms * 3 floats = 3072 floats = 768 float4s.
// Thread t issues stores s=0..2 at float4 index q = s*256 + t, so every
// warp-level STG.128 covers a contiguous 512B span (4 lines — minimum).
// Each float4 straddles two atoms (16B vs 12B/atom): compute both atoms'
// 6 components and select 4 by r = (4q) mod 3.
__global__ __launch_bounds__(THREADS)
void rij_min_image_kernel(const float* __restrict__ pos,
                          const float* __restrict__ cell,
                          float* __restrict__ out)
{
    __shared__ float sx[NATOMS], sy[NATOMS], sz[NATOMS];   // SoA, 12 KB

    const int b  = blockIdx.y;
    const int i0 = blockIdx.x * ITILE;

    // Cooperative SoA fill of this frame's positions.
    const float* pb = pos + (size_t)b * NATOMS * 3;
    #pragma unroll
    for (int a = threadIdx.x; a < NATOMS; a += THREADS) {
        sx[a] = pb[3 * a + 0];
        sy[a] = pb[3 * a + 1];
        sz[a] = pb[3 * a + 2];
    }

    // Box lengths from the cell diagonal; L/2 is exact.
    const float Lx = cell[(size_t)b * 9 + 0];
    const float Ly = cell[(size_t)b * 9 + 4];
    const float Lz = cell[(size_t)b * 9 + 8];
    const float hx = 0.5f * Lx, hy = 0.5f * Ly, hz = 0.5f * Lz;

    __syncthreads();

    // Row-atom positions, cached across the whole block of stores.
    float pix[ITILE], piy[ITILE], piz[ITILE];
    #pragma unroll
    for (int ii = 0; ii < ITILE; ++ii) {
        pix[ii] = sx[i0 + ii];
        piy[ii] = sy[i0 + ii];
        piz[ii] = sz[i0 + ii];
    }

    float* orow = out + ((size_t)b * NATOMS * NATOMS + (size_t)i0 * NATOMS) * 3;

    #pragma unroll
    for (int s = 0; s < 3; ++s) {
        const int q  = s * THREADS + threadIdx.x;   // float4 index in row, 0..767
        const int f0 = 4 * q;                       // first float index
        const int ja = f0 / 3;                      // first atom (<= 1022)
        const int r  = f0 - 3 * ja;                 // 0, 1, or 2

        // Two consecutive column atoms, cached across the ITILE rows.
        const float ax = sx[ja],     ay = sy[ja],     az = sz[ja];
        const float bx = sx[ja + 1], by = sy[ja + 1], bz = sz[ja + 1];

        #pragma unroll
        for (int ii = 0; ii < ITILE; ++ii) {
            const float d0 = min_image(pix[ii] - ax, Lx, hx);
            const float d1 = min_image(piy[ii] - ay, Ly, hy);
            const float d2 = min_image(piz[ii] - az, Lz, hz);
            const float d3 = min_image(pix[ii] - bx, Lx, hx);
            const float d4 = min_image(piy[ii] - by, Ly, hy);
            const float d5 = min_image(piz[ii] - bz, Lz, hz);

            float4 v;
            v.x = (r == 0) ? d0 : ((r == 1) ? d1 : d2);
            v.y = (r == 0) ? d1 : ((r == 1) ? d2 : d3);
            v.z = (r == 0) ? d2 : ((r == 1) ? d3 : d4);
            v.w = (r == 0) ? d3 : ((r == 1) ? d4 : d5);

            __stcs((float4*)(orow + (size_t)ii * NATOMS * 3) + q, v);
        }
    }
}

extern "C" void kernel_launch(void* const* d_in, const int* in_sizes, int n_in,
                              void* d_out, int out_size)
{
    const float* positions = (const float*)d_in[0];  // (32, 1024, 3)
    const float* cell      = (const float*)d_in[1];  // (32, 3, 3)
    float* out             = (float*)d_out;          // (32, 1024, 1024, 3)

    dim3 grid(NATOMS / ITILE, BATCH);   // (256, 32) = 8192 blocks
    rij_min_image_kernel<<<grid, THREADS>>>(positions, cell, out);
}